// round 2
// baseline (speedup 1.0000x reference)
#include <cuda_runtime.h>
#include <math.h>

#define BATCH 4
#define T_SEQ 2048
#define TOK (BATCH*T_SEQ)          // 8192
#define DIMC 512
#define HEADS 8
#define DH 64
#define FRAMES 32

// ---------------- scratch (device globals: allocation-free rule) -------------
static __device__ float g_xn[TOK*DIMC];        // normalized x, tf32-rounded
static __device__ float g_q [TOK*DIMC];        // [B][H][T][64], tf32, pre-scaled 1/8
static __device__ float g_k [TOK*DIMC];        // [B][H][T][64], tf32
static __device__ float g_vt[TOK*DIMC];        // [B][H][64][T]  (transposed V), tf32
static __device__ float g_att[TOK*DIMC];       // attention out [B][T][H*64], tf32
static __device__ float g_wqkv_t[3*DIMC*DIMC]; // [1536][512] transposed, tf32
static __device__ float g_wout_t[DIMC*DIMC];   // [512][512]  transposed, tf32

// ---------------- tf32 helpers ----------------------------------------------
__device__ __forceinline__ unsigned f2tf(float x) {
    unsigned r; asm("cvt.rna.tf32.f32 %0, %1;" : "=r"(r) : "f"(x)); return r;
}
__device__ __forceinline__ float f2tff(float x) {
    return __uint_as_float(f2tf(x));
}
__device__ __forceinline__ void mma8(float* c, unsigned a0, unsigned a1,
                                     unsigned a2, unsigned a3,
                                     unsigned b0, unsigned b1) {
    asm volatile(
        "mma.sync.aligned.m16n8k8.row.col.f32.tf32.tf32.f32 "
        "{%0,%1,%2,%3},{%4,%5,%6,%7},{%8,%9},{%0,%1,%2,%3};\n"
        : "+f"(c[0]), "+f"(c[1]), "+f"(c[2]), "+f"(c[3])
        : "r"(a0), "r"(a1), "r"(a2), "r"(a3), "r"(b0), "r"(b1));
}

// ---------------- 0) transpose + tf32-convert weights ------------------------
// dst[c][r] = tf32(src[r][c]); src is [R][C] row-major.
__global__ __launch_bounds__(256) void tr_cvt(
    const float* __restrict__ src, float* __restrict__ dst, int R, int C)
{
    __shared__ float t[32][33];
    int c0 = blockIdx.x * 32, r0 = blockIdx.y * 32;
    int tx = threadIdx.x, ty = threadIdx.y;       // 32 x 8
#pragma unroll
    for (int j = 0; j < 4; j++)
        t[ty + j*8][tx] = src[(size_t)(r0 + ty + j*8) * C + c0 + tx];
    __syncthreads();
#pragma unroll
    for (int j = 0; j < 4; j++)
        dst[(size_t)(c0 + ty + j*8) * R + r0 + tx] = f2tff(t[tx][ty + j*8]);
}

// ---------------- 1) LayerNorm: one warp per token, tf32 output --------------
__global__ __launch_bounds__(256) void ln_kernel(
    const float* __restrict__ x, const float* __restrict__ gam,
    const float* __restrict__ bet)
{
    int warp = threadIdx.x >> 5, lane = threadIdx.x & 31;
    int tok  = blockIdx.x * 8 + warp;
    const float* xr = x + (size_t)tok * DIMC;
    float4 v[4]; float s = 0.f, ss = 0.f;
#pragma unroll
    for (int i = 0; i < 4; i++) {
        v[i] = *(const float4*)(xr + i * 128 + lane * 4);
        s  += v[i].x + v[i].y + v[i].z + v[i].w;
        ss += v[i].x*v[i].x + v[i].y*v[i].y + v[i].z*v[i].z + v[i].w*v[i].w;
    }
#pragma unroll
    for (int o = 16; o > 0; o >>= 1) {
        s  += __shfl_xor_sync(0xffffffffu, s, o);
        ss += __shfl_xor_sync(0xffffffffu, ss, o);
    }
    float mean = s * (1.f/512.f);
    float var  = ss * (1.f/512.f) - mean*mean;
    float rstd = rsqrtf(var + 1e-5f);
    float* orow = g_xn + (size_t)tok * DIMC;
#pragma unroll
    for (int i = 0; i < 4; i++) {
        int col = i * 128 + lane * 4;
        float4 g4 = *(const float4*)(gam + col);
        float4 b4 = *(const float4*)(bet + col);
        float4 r;
        r.x = f2tff((v[i].x - mean) * rstd * g4.x + b4.x);
        r.y = f2tff((v[i].y - mean) * rstd * g4.y + b4.y);
        r.z = f2tff((v[i].z - mean) * rstd * g4.z + b4.z);
        r.w = f2tff((v[i].w - mean) * rstd * g4.w + b4.w);
        *(float4*)(orow + col) = r;
    }
}

// k-group permutation: logical col c (0..7) -> physical ((c&3)<<1)|(c>>2)
// pairs (t4, t4+4) land at (2*t4, 2*t4+1) => one LDS.64 per mma fragment pair.

#define AS_STR 36
#define BS_STR 36

// ---------------- 2) QKV GEMM: 128x64x32 tiles, paired-LDS tf32 mma ----------
__global__ __launch_bounds__(256) void qkv_gemm(void)
{
    __shared__ float As[128][AS_STR];   // k-permuted
    __shared__ float Bs[64][BS_STR];    // rows = n, k-permuted (from transposed W)
    const int K = DIMC;
    int tid = threadIdx.x, warp = tid >> 5, lane = tid & 31;
    int g = lane >> 2, t4 = lane & 3;
    int wm = warp >> 1, wn = warp & 1;
    int row0 = blockIdx.y * 128, col0 = blockIdx.x * 64;
    const float* A  = g_xn;
    const float* Bt = g_wqkv_t;         // [1536][512]
    float c[2][4][4] = {};

    for (int k0 = 0; k0 < K; k0 += 32) {
#pragma unroll
        for (int t = 0; t < 2; t++) {                     // A tile 128x32
            int a = tid + t * 256;
            int r = a >> 2, g8 = a & 3;
            const float* p = A + (size_t)(row0 + r) * K + k0 + g8 * 8;
            float4 lo = *(const float4*)p;
            float4 hi = *(const float4*)(p + 4);
            float2* dstp = (float2*)&As[r][g8 * 8];
            dstp[0] = make_float2(lo.x, hi.x);
            dstp[1] = make_float2(lo.y, hi.y);
            dstp[2] = make_float2(lo.z, hi.z);
            dstp[3] = make_float2(lo.w, hi.w);
        }
        {                                                  // B tile 64x32
            int r = tid >> 2, g8 = tid & 3;
            const float* p = Bt + (size_t)(col0 + r) * K + k0 + g8 * 8;
            float4 lo = *(const float4*)p;
            float4 hi = *(const float4*)(p + 4);
            float2* dstp = (float2*)&Bs[r][g8 * 8];
            dstp[0] = make_float2(lo.x, hi.x);
            dstp[1] = make_float2(lo.y, hi.y);
            dstp[2] = make_float2(lo.z, hi.z);
            dstp[3] = make_float2(lo.w, hi.w);
        }
        __syncthreads();
#pragma unroll
        for (int ks = 0; ks < 4; ks++) {
            int kb = ks * 8;
            float2 a01[2], a23[2], b[4];
#pragma unroll
            for (int mi = 0; mi < 2; mi++) {
                int rb = wm * 32 + mi * 16;
                a01[mi] = *(const float2*)&As[rb + g    ][kb + 2 * t4];
                a23[mi] = *(const float2*)&As[rb + g + 8][kb + 2 * t4];
            }
#pragma unroll
            for (int ni = 0; ni < 4; ni++)
                b[ni] = *(const float2*)&Bs[wn * 32 + ni * 8 + g][kb + 2 * t4];
#pragma unroll
            for (int mi = 0; mi < 2; mi++)
#pragma unroll
                for (int ni = 0; ni < 4; ni++)
                    mma8(c[mi][ni],
                         __float_as_uint(a01[mi].x), __float_as_uint(a23[mi].x),
                         __float_as_uint(a01[mi].y), __float_as_uint(a23[mi].y),
                         __float_as_uint(b[ni].x),   __float_as_uint(b[ni].y));
        }
        __syncthreads();
    }
    // epilogue: block covers one of q/k/v and one head
    int which = col0 >> 9;
    int h = (col0 & 511) >> 6;
    if (which < 2) {
        float* dst = (which == 0) ? g_q : g_k;
        float sc = (which == 0) ? 0.125f : 1.0f;
#pragma unroll
        for (int mi = 0; mi < 2; mi++) {
            int r0 = row0 + wm * 32 + mi * 16 + g;
            int r1 = r0 + 8;
            int bb = r0 >> 11;
            int t0i = r0 & 2047, t1i = r1 & 2047;
            size_t base = (((size_t)bb * HEADS + h) * T_SEQ) * DH;
#pragma unroll
            for (int ni = 0; ni < 4; ni++) {
                int d = wn * 32 + ni * 8 + t4 * 2;
                size_t i0 = base + (size_t)t0i * DH + d;
                size_t i1 = base + (size_t)t1i * DH + d;
                dst[i0]     = f2tff(c[mi][ni][0] * sc);
                dst[i0 + 1] = f2tff(c[mi][ni][1] * sc);
                dst[i1]     = f2tff(c[mi][ni][2] * sc);
                dst[i1 + 1] = f2tff(c[mi][ni][3] * sc);
            }
        }
    } else {
        // V: store transposed [b][h][dh][T]
#pragma unroll
        for (int mi = 0; mi < 2; mi++) {
            int r0 = row0 + wm * 32 + mi * 16 + g;
            int r1 = r0 + 8;
            int bb = r0 >> 11;
            int t0i = r0 & 2047, t1i = r1 & 2047;
            size_t base = (((size_t)bb * HEADS + h) * DH) * T_SEQ;
#pragma unroll
            for (int ni = 0; ni < 4; ni++) {
                int d = wn * 32 + ni * 8 + t4 * 2;
                g_vt[base + (size_t)(d    ) * T_SEQ + t0i] = f2tff(c[mi][ni][0]);
                g_vt[base + (size_t)(d + 1) * T_SEQ + t0i] = f2tff(c[mi][ni][1]);
                g_vt[base + (size_t)(d    ) * T_SEQ + t1i] = f2tff(c[mi][ni][2]);
                g_vt[base + (size_t)(d + 1) * T_SEQ + t1i] = f2tff(c[mi][ni][3]);
            }
        }
    }
}

// ---------------- 3) frame-causal flash attention ----------------------------
#define QS_STR 68
#define KS_STR 68
#define VS_STR 68
#define PS_STR 68
#define ATTN_SMEM ((64*QS_STR + 64*KS_STR + 64*VS_STR + 64*PS_STR) * 4)

__global__ __launch_bounds__(128) void attn_kernel(void)
{
    extern __shared__ float sm[];
    float* Qs  = sm;                    // [64 q][68], dh-permuted
    float* Ks  = Qs + 64 * QS_STR;      // [64 key][68], dh-permuted
    float* Vst = Ks + 64 * KS_STR;      // [64 dh][68], key-permuted (from g_vt)
    float* Ps  = Vst + 64 * VS_STR;     // 4 warps x [16 q][68], key-permuted

    int f = 31 - blockIdx.x;            // heavy frames first
    int h = blockIdx.y, b = blockIdx.z;
    int tid = threadIdx.x, warp = tid >> 5, lane = tid & 31;
    int g = lane >> 2, t4 = lane & 3;
    size_t bh = ((size_t)b * HEADS + h) * T_SEQ * DH;
    const float* qb  = g_q  + bh;
    const float* kb  = g_k  + bh;
    const float* vtb = g_vt + bh;       // [64 dh][T]
    int t0 = f * 64;

    // load Q tile: 64 rows x 8 dh-groups, 4 assignments/thread
#pragma unroll
    for (int i = 0; i < 4; i++) {
        int a = tid + i * 128;
        int r = a >> 3, g8 = a & 7;
        const float* p = qb + (size_t)(t0 + r) * DH + g8 * 8;
        float4 lo = *(const float4*)p;
        float4 hi = *(const float4*)(p + 4);
        float2* dstp = (float2*)&Qs[r * QS_STR + g8 * 8];
        dstp[0] = make_float2(lo.x, hi.x);
        dstp[1] = make_float2(lo.y, hi.y);
        dstp[2] = make_float2(lo.z, hi.z);
        dstp[3] = make_float2(lo.w, hi.w);
    }

    float m0 = -1e30f, m1 = -1e30f, l0 = 0.f, l1 = 0.f;
    float o[8][4] = {};
    float* Pw = Ps + warp * 16 * PS_STR;
    int wrow = warp * 16;
    // physical columns for P store (logical 2*t4, 2*t4+1)
    int c0l = 2 * t4, c1l = c0l + 1;
    int p0 = ((c0l & 3) << 1) | (c0l >> 2);
    int p1 = ((c1l & 3) << 1) | (c1l >> 2);

    for (int kt = 0; kt <= f; kt++) {
        int kt0 = kt * 64;
#pragma unroll
        for (int i = 0; i < 4; i++) {   // K tile [64 key][64 dh]
            int a = tid + i * 128;
            int r = a >> 3, g8 = a & 7;
            const float* p = kb + (size_t)(kt0 + r) * DH + g8 * 8;
            float4 lo = *(const float4*)p;
            float4 hi = *(const float4*)(p + 4);
            float2* dstp = (float2*)&Ks[r * KS_STR + g8 * 8];
            dstp[0] = make_float2(lo.x, hi.x);
            dstp[1] = make_float2(lo.y, hi.y);
            dstp[2] = make_float2(lo.z, hi.z);
            dstp[3] = make_float2(lo.w, hi.w);
        }
#pragma unroll
        for (int i = 0; i < 4; i++) {   // V tile transposed [64 dh][64 key]
            int a = tid + i * 128;
            int r = a >> 3, g8 = a & 7; // r = dh, g8 = key group
            const float* p = vtb + (size_t)r * T_SEQ + kt0 + g8 * 8;
            float4 lo = *(const float4*)p;
            float4 hi = *(const float4*)(p + 4);
            float2* dstp = (float2*)&Vst[r * VS_STR + g8 * 8];
            dstp[0] = make_float2(lo.x, hi.x);
            dstp[1] = make_float2(lo.y, hi.y);
            dstp[2] = make_float2(lo.z, hi.z);
            dstp[3] = make_float2(lo.w, hi.w);
        }
        __syncthreads();

        // S = Q K^T : 16 q rows x 64 keys per warp
        float s[8][4] = {};
#pragma unroll
        for (int ks = 0; ks < 8; ks++) {
            int kc = ks * 8;
            float2 a01 = *(const float2*)&Qs[(wrow + g    ) * QS_STR + kc + 2 * t4];
            float2 a23 = *(const float2*)&Qs[(wrow + g + 8) * QS_STR + kc + 2 * t4];
#pragma unroll
            for (int n = 0; n < 8; n++) {
                float2 bb2 = *(const float2*)&Ks[(n * 8 + g) * KS_STR + kc + 2 * t4];
                mma8(s[n],
                     __float_as_uint(a01.x), __float_as_uint(a23.x),
                     __float_as_uint(a01.y), __float_as_uint(a23.y),
                     __float_as_uint(bb2.x), __float_as_uint(bb2.y));
            }
        }

        // online softmax
        float mx0 = -1e30f, mx1 = -1e30f;
#pragma unroll
        for (int n = 0; n < 8; n++) {
            mx0 = fmaxf(mx0, fmaxf(s[n][0], s[n][1]));
            mx1 = fmaxf(mx1, fmaxf(s[n][2], s[n][3]));
        }
        mx0 = fmaxf(mx0, __shfl_xor_sync(0xffffffffu, mx0, 1));
        mx0 = fmaxf(mx0, __shfl_xor_sync(0xffffffffu, mx0, 2));
        mx1 = fmaxf(mx1, __shfl_xor_sync(0xffffffffu, mx1, 1));
        mx1 = fmaxf(mx1, __shfl_xor_sync(0xffffffffu, mx1, 2));
        float mn0 = fmaxf(m0, mx0), mn1 = fmaxf(m1, mx1);
        float al0 = __expf(m0 - mn0), al1 = __expf(m1 - mn1);
        float sum0 = 0.f, sum1 = 0.f;
#pragma unroll
        for (int n = 0; n < 8; n++) {
            s[n][0] = __expf(s[n][0] - mn0);
            s[n][1] = __expf(s[n][1] - mn0);
            s[n][2] = __expf(s[n][2] - mn1);
            s[n][3] = __expf(s[n][3] - mn1);
            sum0 += s[n][0] + s[n][1];
            sum1 += s[n][2] + s[n][3];
        }
        sum0 += __shfl_xor_sync(0xffffffffu, sum0, 1);
        sum0 += __shfl_xor_sync(0xffffffffu, sum0, 2);
        sum1 += __shfl_xor_sync(0xffffffffu, sum1, 1);
        sum1 += __shfl_xor_sync(0xffffffffu, sum1, 2);
        l0 = l0 * al0 + sum0;  l1 = l1 * al1 + sum1;
        m0 = mn0;  m1 = mn1;
#pragma unroll
        for (int n = 0; n < 8; n++) {
            o[n][0] *= al0; o[n][1] *= al0;
            o[n][2] *= al1; o[n][3] *= al1;
        }

        // stage tf32 P in per-warp SMEM (key-permuted)
#pragma unroll
        for (int n = 0; n < 8; n++) {
            Pw[ g      * PS_STR + n * 8 + p0] = f2tff(s[n][0]);
            Pw[ g      * PS_STR + n * 8 + p1] = f2tff(s[n][1]);
            Pw[(g + 8) * PS_STR + n * 8 + p0] = f2tff(s[n][2]);
            Pw[(g + 8) * PS_STR + n * 8 + p1] = f2tff(s[n][3]);
        }
        __syncwarp();

        // O += P * V   (A = P [16q x 64key], B = V^T [key x dh] via Vst[dh][key])
#pragma unroll
        for (int ks = 0; ks < 8; ks++) {
            int kc = ks * 8;
            float2 a01 = *(const float2*)&Pw[ g      * PS_STR + kc + 2 * t4];
            float2 a23 = *(const float2*)&Pw[(g + 8) * PS_STR + kc + 2 * t4];
#pragma unroll
            for (int n = 0; n < 8; n++) {
                float2 bb2 = *(const float2*)&Vst[(n * 8 + g) * VS_STR + kc + 2 * t4];
                mma8(o[n],
                     __float_as_uint(a01.x), __float_as_uint(a23.x),
                     __float_as_uint(a01.y), __float_as_uint(a23.y),
                     __float_as_uint(bb2.x), __float_as_uint(bb2.y));
            }
        }
        __syncthreads();
    }

    float inv0 = 1.f / l0, inv1 = 1.f / l1;
    int q0 = t0 + wrow + g, q1 = q0 + 8;
    float* out0 = g_att + ((size_t)b * T_SEQ + q0) * DIMC + h * DH;
    float* out1 = g_att + ((size_t)b * T_SEQ + q1) * DIMC + h * DH;
#pragma unroll
    for (int n = 0; n < 8; n++) {
        int cc = n * 8 + t4 * 2;
        out0[cc]     = f2tff(o[n][0] * inv0);
        out0[cc + 1] = f2tff(o[n][1] * inv0);
        out1[cc]     = f2tff(o[n][2] * inv1);
        out1[cc + 1] = f2tff(o[n][3] * inv1);
    }
}

// ---------------- 4) output GEMM + bias --------------------------------------
__global__ __launch_bounds__(256) void out_gemm(
    const float* __restrict__ bias, float* __restrict__ out)
{
    __shared__ float As[128][AS_STR];
    __shared__ float Bs[64][BS_STR];
    const int N = DIMC, K = DIMC;
    int tid = threadIdx.x, warp = tid >> 5, lane = tid & 31;
    int g = lane >> 2, t4 = lane & 3;
    int wm = warp >> 1, wn = warp & 1;
    int row0 = blockIdx.y * 128, col0 = blockIdx.x * 64;
    const float* A  = g_att;
    const float* Bt = g_wout_t;         // [512][512] transposed
    float c[2][4][4] = {};

    for (int k0 = 0; k0 < K; k0 += 32) {
#pragma unroll
        for (int t = 0; t < 2; t++) {
            int a = tid + t * 256;
            int r = a >> 2, g8 = a & 3;
            const float* p = A + (size_t)(row0 + r) * K + k0 + g8 * 8;
            float4 lo = *(const float4*)p;
            float4 hi = *(const float4*)(p + 4);
            float2* dstp = (float2*)&As[r][g8 * 8];
            dstp[0] = make_float2(lo.x, hi.x);
            dstp[1] = make_float2(lo.y, hi.y);
            dstp[2] = make_float2(lo.z, hi.z);
            dstp[3] = make_float2(lo.w, hi.w);
        }
        {
            int r = tid >> 2, g8 = tid & 3;
            const float* p = Bt + (size_t)(col0 + r) * K + k0 + g8 * 8;
            float4 lo = *(const float4*)p;
            float4 hi = *(const float4*)(p + 4);
            float2* dstp = (float2*)&Bs[r][g8 * 8];
            dstp[0] = make_float2(lo.x, hi.x);
            dstp[1] = make_float2(lo.y, hi.y);
            dstp[2] = make_float2(lo.z, hi.z);
            dstp[3] = make_float2(lo.w, hi.w);
        }
        __syncthreads();
#pragma unroll
        for (int ks = 0; ks < 4; ks++) {
            int kb = ks * 8;
            float2 a01[2], a23[2], b[4];
#pragma unroll
            for (int mi = 0; mi < 2; mi++) {
                int rb = wm * 32 + mi * 16;
                a01[mi] = *(const float2*)&As[rb + g    ][kb + 2 * t4];
                a23[mi] = *(const float2*)&As[rb + g + 8][kb + 2 * t4];
            }
#pragma unroll
            for (int ni = 0; ni < 4; ni++)
                b[ni] = *(const float2*)&Bs[wn * 32 + ni * 8 + g][kb + 2 * t4];
#pragma unroll
            for (int mi = 0; mi < 2; mi++)
#pragma unroll
                for (int ni = 0; ni < 4; ni++)
                    mma8(c[mi][ni],
                         __float_as_uint(a01[mi].x), __float_as_uint(a23[mi].x),
                         __float_as_uint(a01[mi].y), __float_as_uint(a23[mi].y),
                         __float_as_uint(b[ni].x),   __float_as_uint(b[ni].y));
        }
        __syncthreads();
    }
#pragma unroll
    for (int mi = 0; mi < 2; mi++) {
        int r0 = row0 + wm * 32 + mi * 16 + g;
        int r1 = r0 + 8;
#pragma unroll
        for (int ni = 0; ni < 4; ni++) {
            int col = col0 + wn * 32 + ni * 8 + t4 * 2;
            float bz0 = bias[col], bz1 = bias[col + 1];
            out[(size_t)r0 * N + col]     = c[mi][ni][0] + bz0;
            out[(size_t)r0 * N + col + 1] = c[mi][ni][1] + bz1;
            out[(size_t)r1 * N + col]     = c[mi][ni][2] + bz0;
            out[(size_t)r1 * N + col + 1] = c[mi][ni][3] + bz1;
        }
    }
}

// ---------------- launch -----------------------------------------------------
extern "C" void kernel_launch(void* const* d_in, const int* in_sizes, int n_in,
                              void* d_out, int out_size)
{
    (void)in_sizes; (void)n_in; (void)out_size;
    const float* x     = (const float*)d_in[0];
    const float* ln_g  = (const float*)d_in[1];
    const float* ln_b  = (const float*)d_in[2];
    const float* w_qkv = (const float*)d_in[3];
    const float* w_out = (const float*)d_in[4];
    const float* b_out = (const float*)d_in[5];
    float* out = (float*)d_out;

    cudaFuncSetAttribute(attn_kernel,
                         cudaFuncAttributeMaxDynamicSharedMemorySize, ATTN_SMEM);

    float *wqkv_t, *wout_t;
    cudaGetSymbolAddress((void**)&wqkv_t, g_wqkv_t);
    cudaGetSymbolAddress((void**)&wout_t, g_wout_t);

    tr_cvt<<<dim3(3*DIMC/32, DIMC/32), dim3(32, 8)>>>(w_qkv, wqkv_t, DIMC, 3*DIMC);
    tr_cvt<<<dim3(DIMC/32, DIMC/32), dim3(32, 8)>>>(w_out, wout_t, DIMC, DIMC);
    ln_kernel<<<TOK / 8, 256>>>(x, ln_g, ln_b);
    qkv_gemm<<<dim3(3 * DIMC / 64, TOK / 128), 256>>>();
    attn_kernel<<<dim3(FRAMES, HEADS, BATCH), 128, ATTN_SMEM>>>();
    out_gemm<<<dim3(DIMC / 64, TOK / 128), 256>>>(b_out, out);
}

// round 3
// speedup vs baseline: 1.5699x; 1.5699x over previous
#include <cuda_runtime.h>
#include <math.h>

#define BATCH 4
#define T_SEQ 2048
#define TOK (BATCH*T_SEQ)          // 8192
#define DIMC 512
#define HEADS 8
#define DH 64
#define FRAMES 32

// ---------------- scratch (device globals: allocation-free rule) -------------
static __device__ float g_xn[TOK*DIMC];        // normalized x, tf32-rounded
static __device__ float g_q [TOK*DIMC];        // [B][H][T][64], tf32, pre-scaled 1/8
static __device__ float g_k [TOK*DIMC];        // [B][H][T][64], tf32
static __device__ float g_v [TOK*DIMC];        // [B][H][T][64], tf32
static __device__ float g_att[TOK*DIMC];       // attention out [B][T][H*64], tf32
static __device__ float g_wqkv_t[3*DIMC*DIMC]; // [1536][512] transposed, tf32
static __device__ float g_wout_t[DIMC*DIMC];   // [512][512]  transposed, tf32

// ---------------- tf32 helpers ----------------------------------------------
__device__ __forceinline__ unsigned f2tf(float x) {
    unsigned r; asm("cvt.rna.tf32.f32 %0, %1;" : "=r"(r) : "f"(x)); return r;
}
__device__ __forceinline__ float f2tff(float x) {
    return __uint_as_float(f2tf(x));
}
__device__ __forceinline__ unsigned fu(float x) { return __float_as_uint(x); }

// k-relabel convention: mma slot (t4, t4+4) <- logical k cols (2t4, 2t4+1).
// Valid because A and B use the SAME k mapping; reduction order is irrelevant.
__device__ __forceinline__ void mma8(float* c, unsigned a0, unsigned a1,
                                     unsigned a2, unsigned a3,
                                     unsigned b0, unsigned b1) {
    asm volatile(
        "mma.sync.aligned.m16n8k8.row.col.f32.tf32.tf32.f32 "
        "{%0,%1,%2,%3},{%4,%5,%6,%7},{%8,%9},{%0,%1,%2,%3};\n"
        : "+f"(c[0]), "+f"(c[1]), "+f"(c[2]), "+f"(c[3])
        : "r"(a0), "r"(a1), "r"(a2), "r"(a3), "r"(b0), "r"(b1));
}

// ---------------- 0) transpose + tf32-convert weights ------------------------
__global__ __launch_bounds__(256) void tr_cvt(
    const float* __restrict__ src, float* __restrict__ dst, int R, int C)
{
    __shared__ float t[32][33];
    int c0 = blockIdx.x * 32, r0 = blockIdx.y * 32;
    int tx = threadIdx.x, ty = threadIdx.y;       // 32 x 8
#pragma unroll
    for (int j = 0; j < 4; j++)
        t[ty + j*8][tx] = src[(size_t)(r0 + ty + j*8) * C + c0 + tx];
    __syncthreads();
#pragma unroll
    for (int j = 0; j < 4; j++)
        dst[(size_t)(c0 + ty + j*8) * R + r0 + tx] = f2tff(t[tx][ty + j*8]);
}

// ---------------- 1) LayerNorm: one warp per token, tf32 output --------------
__global__ __launch_bounds__(256) void ln_kernel(
    const float* __restrict__ x, const float* __restrict__ gam,
    const float* __restrict__ bet)
{
    int warp = threadIdx.x >> 5, lane = threadIdx.x & 31;
    int tok  = blockIdx.x * 8 + warp;
    const float* xr = x + (size_t)tok * DIMC;
    float4 v[4]; float s = 0.f, ss = 0.f;
#pragma unroll
    for (int i = 0; i < 4; i++) {
        v[i] = *(const float4*)(xr + i * 128 + lane * 4);
        s  += v[i].x + v[i].y + v[i].z + v[i].w;
        ss += v[i].x*v[i].x + v[i].y*v[i].y + v[i].z*v[i].z + v[i].w*v[i].w;
    }
#pragma unroll
    for (int o = 16; o > 0; o >>= 1) {
        s  += __shfl_xor_sync(0xffffffffu, s, o);
        ss += __shfl_xor_sync(0xffffffffu, ss, o);
    }
    float mean = s * (1.f/512.f);
    float var  = ss * (1.f/512.f) - mean*mean;
    float rstd = rsqrtf(var + 1e-5f);
    float* orow = g_xn + (size_t)tok * DIMC;
#pragma unroll
    for (int i = 0; i < 4; i++) {
        int col = i * 128 + lane * 4;
        float4 g4 = *(const float4*)(gam + col);
        float4 b4 = *(const float4*)(bet + col);
        float4 r;
        r.x = f2tff((v[i].x - mean) * rstd * g4.x + b4.x);
        r.y = f2tff((v[i].y - mean) * rstd * g4.y + b4.y);
        r.z = f2tff((v[i].z - mean) * rstd * g4.z + b4.z);
        r.w = f2tff((v[i].w - mean) * rstd * g4.w + b4.w);
        *(float4*)(orow + col) = r;
    }
}

#define GS_STR 40   // GEMM smem stride: (40*g + 2*t4) % 32 = 8g+2t4 -> conflict-free

// ---------------- 2) QKV GEMM: 128x64x32 tiles, paired-LDS tf32 mma ----------
__global__ __launch_bounds__(256) void qkv_gemm(void)
{
    __shared__ float As[128][GS_STR];   // row-major [m][k]
    __shared__ float Bs[64][GS_STR];    // row-major [n][k] (from transposed W)
    const int K = DIMC;
    int tid = threadIdx.x, warp = tid >> 5, lane = tid & 31;
    int g = lane >> 2, t4 = lane & 3;
    int wm = warp >> 1, wn = warp & 1;
    int row0 = blockIdx.y * 128, col0 = blockIdx.x * 64;
    const float* A  = g_xn;
    const float* Bt = g_wqkv_t;
    float c[2][4][4] = {};

    for (int k0 = 0; k0 < K; k0 += 32) {
#pragma unroll
        for (int t = 0; t < 4; t++) {                     // A tile 128x32
            int a = tid + t * 256;
            int r = a >> 3, c4 = (a & 7) * 4;
            *(float4*)&As[r][c4] = *(const float4*)(A + (size_t)(row0 + r) * K + k0 + c4);
        }
#pragma unroll
        for (int t = 0; t < 2; t++) {                     // B tile 64x32
            int a = tid + t * 256;
            int r = a >> 3, c4 = (a & 7) * 4;
            *(float4*)&Bs[r][c4] = *(const float4*)(Bt + (size_t)(col0 + r) * K + k0 + c4);
        }
        __syncthreads();
#pragma unroll
        for (int ks = 0; ks < 4; ks++) {
            int kb = ks * 8 + 2 * t4;
            float2 a01[2], a23[2], b[4];
#pragma unroll
            for (int mi = 0; mi < 2; mi++) {
                int rb = wm * 32 + mi * 16;
                a01[mi] = *(const float2*)&As[rb + g    ][kb];
                a23[mi] = *(const float2*)&As[rb + g + 8][kb];
            }
#pragma unroll
            for (int ni = 0; ni < 4; ni++)
                b[ni] = *(const float2*)&Bs[wn * 32 + ni * 8 + g][kb];
#pragma unroll
            for (int mi = 0; mi < 2; mi++)
#pragma unroll
                for (int ni = 0; ni < 4; ni++)
                    mma8(c[mi][ni], fu(a01[mi].x), fu(a23[mi].x),
                         fu(a01[mi].y), fu(a23[mi].y), fu(b[ni].x), fu(b[ni].y));
        }
        __syncthreads();
    }
    // epilogue: block covers one of q/k/v and one head; row-major [B][H][T][64]
    int which = col0 >> 9;
    int h = (col0 & 511) >> 6;
    float* dst = (which == 0) ? g_q : ((which == 1) ? g_k : g_v);
    float sc = (which == 0) ? 0.125f : 1.0f;
#pragma unroll
    for (int mi = 0; mi < 2; mi++) {
        int r0 = row0 + wm * 32 + mi * 16 + g;
        int r1 = r0 + 8;
        int bb = r0 >> 11;
        int t0i = r0 & 2047, t1i = r1 & 2047;
        size_t base = (((size_t)bb * HEADS + h) * T_SEQ) * DH;
#pragma unroll
        for (int ni = 0; ni < 4; ni++) {
            int d = wn * 32 + ni * 8 + t4 * 2;
            size_t i0 = base + (size_t)t0i * DH + d;
            size_t i1 = base + (size_t)t1i * DH + d;
            dst[i0]     = f2tff(c[mi][ni][0] * sc);
            dst[i0 + 1] = f2tff(c[mi][ni][1] * sc);
            dst[i1]     = f2tff(c[mi][ni][2] * sc);
            dst[i1 + 1] = f2tff(c[mi][ni][3] * sc);
        }
    }
}

// ---------------- 3) frame-causal flash attention ----------------------------
// smem strides: Ks/Ps 72 -> (72g+2t4)%32 = 8g+2t4 conflict-free LDS.64
//               Vs 68    -> (68*2*t4)%32 = 8t4, +g+8n -> conflict-free LDS.32
#define KS_STR 72
#define VS_STR 68
#define PS_STR 72
#define ATTN_SMEM ((64*KS_STR + 64*VS_STR + 64*PS_STR) * 4)

__global__ __launch_bounds__(128) void attn_kernel(void)
{
    extern __shared__ float sm[];
    float* Ks = sm;                     // [64 key][64 dh] row-major
    float* Vs = Ks + 64 * KS_STR;       // [64 key][64 dh] row-major
    float* Ps = Vs + 64 * VS_STR;       // 4 warps x [16 q][64 key]

    int f = 31 - blockIdx.x;            // heavy frames first
    int h = blockIdx.y, b = blockIdx.z;
    int tid = threadIdx.x, warp = tid >> 5, lane = tid & 31;
    int g = lane >> 2, t4 = lane & 3;
    size_t bh = ((size_t)b * HEADS + h) * T_SEQ * DH;
    const float* qb = g_q + bh;
    const float* kb = g_k + bh;
    const float* vb = g_v + bh;
    int t0 = f * 64;
    int wrow = warp * 16;
    float* Pw = Ps + warp * 16 * PS_STR;

    // stage Q through Ks, pull this warp's a-fragments into registers
#pragma unroll
    for (int i = 0; i < 8; i++) {
        int a = tid + i * 128;
        int r = a >> 4, c4 = (a & 15) * 4;
        *(float4*)&Ks[r * KS_STR + c4] = *(const float4*)(qb + (size_t)(t0 + r) * DH + c4);
    }
    __syncthreads();
    float2 qa[8][2];
#pragma unroll
    for (int ks = 0; ks < 8; ks++) {
        int kc = ks * 8 + 2 * t4;
        qa[ks][0] = *(const float2*)&Ks[(wrow + g    ) * KS_STR + kc];
        qa[ks][1] = *(const float2*)&Ks[(wrow + g + 8) * KS_STR + kc];
    }
    __syncthreads();

    float m0 = -1e30f, m1 = -1e30f, l0 = 0.f, l1 = 0.f;
    float o[8][4] = {};

    for (int kt = 0; kt <= f; kt++) {
        int kt0 = kt * 64;
#pragma unroll
        for (int i = 0; i < 8; i++) {
            int a = tid + i * 128;
            int r = a >> 4, c4 = (a & 15) * 4;
            *(float4*)&Ks[r * KS_STR + c4] = *(const float4*)(kb + (size_t)(kt0 + r) * DH + c4);
            *(float4*)&Vs[r * VS_STR + c4] = *(const float4*)(vb + (size_t)(kt0 + r) * DH + c4);
        }
        __syncthreads();

        // S = Q K^T : 16 q rows x 64 keys per warp
        float s[8][4] = {};
#pragma unroll
        for (int ks = 0; ks < 8; ks++) {
            int kc = ks * 8 + 2 * t4;
#pragma unroll
            for (int n = 0; n < 8; n++) {
                float2 b2 = *(const float2*)&Ks[(n * 8 + g) * KS_STR + kc];
                mma8(s[n], fu(qa[ks][0].x), fu(qa[ks][1].x),
                     fu(qa[ks][0].y), fu(qa[ks][1].y), fu(b2.x), fu(b2.y));
            }
        }

        // online softmax (rows g, g+8 of this warp's strip)
        float mx0 = -1e30f, mx1 = -1e30f;
#pragma unroll
        for (int n = 0; n < 8; n++) {
            mx0 = fmaxf(mx0, fmaxf(s[n][0], s[n][1]));
            mx1 = fmaxf(mx1, fmaxf(s[n][2], s[n][3]));
        }
        mx0 = fmaxf(mx0, __shfl_xor_sync(0xffffffffu, mx0, 1));
        mx0 = fmaxf(mx0, __shfl_xor_sync(0xffffffffu, mx0, 2));
        mx1 = fmaxf(mx1, __shfl_xor_sync(0xffffffffu, mx1, 1));
        mx1 = fmaxf(mx1, __shfl_xor_sync(0xffffffffu, mx1, 2));
        float mn0 = fmaxf(m0, mx0), mn1 = fmaxf(m1, mx1);
        float al0 = __expf(m0 - mn0), al1 = __expf(m1 - mn1);
        float sum0 = 0.f, sum1 = 0.f;
#pragma unroll
        for (int n = 0; n < 8; n++) {
            s[n][0] = __expf(s[n][0] - mn0);
            s[n][1] = __expf(s[n][1] - mn0);
            s[n][2] = __expf(s[n][2] - mn1);
            s[n][3] = __expf(s[n][3] - mn1);
            sum0 += s[n][0] + s[n][1];
            sum1 += s[n][2] + s[n][3];
        }
        sum0 += __shfl_xor_sync(0xffffffffu, sum0, 1);
        sum0 += __shfl_xor_sync(0xffffffffu, sum0, 2);
        sum1 += __shfl_xor_sync(0xffffffffu, sum1, 1);
        sum1 += __shfl_xor_sync(0xffffffffu, sum1, 2);
        l0 = l0 * al0 + sum0;  l1 = l1 * al1 + sum1;
        m0 = mn0;  m1 = mn1;
#pragma unroll
        for (int n = 0; n < 8; n++) {
            o[n][0] *= al0; o[n][1] *= al0;
            o[n][2] *= al1; o[n][3] *= al1;
        }

        // stage tf32 P: C cols (2t4, 2t4+1) are adjacent -> STS.64
#pragma unroll
        for (int n = 0; n < 8; n++) {
            int cc = n * 8 + 2 * t4;
            *(float2*)&Pw[ g      * PS_STR + cc] = make_float2(f2tff(s[n][0]), f2tff(s[n][1]));
            *(float2*)&Pw[(g + 8) * PS_STR + cc] = make_float2(f2tff(s[n][2]), f2tff(s[n][3]));
        }
        __syncwarp();

        // O += P * V  (A = P, B[k=key][n=dh] = Vs row-major)
#pragma unroll
        for (int ks = 0; ks < 8; ks++) {
            int kc = ks * 8 + 2 * t4;
            float2 a01 = *(const float2*)&Pw[ g      * PS_STR + kc];
            float2 a23 = *(const float2*)&Pw[(g + 8) * PS_STR + kc];
            const float* v0 = &Vs[(kc    ) * VS_STR + g];
            const float* v1 = &Vs[(kc + 1) * VS_STR + g];
#pragma unroll
            for (int n = 0; n < 8; n++) {
                mma8(o[n], fu(a01.x), fu(a23.x), fu(a01.y), fu(a23.y),
                     fu(v0[n * 8]), fu(v1[n * 8]));
            }
        }
        __syncthreads();
    }

    float inv0 = 1.f / l0, inv1 = 1.f / l1;
    int q0 = t0 + wrow + g, q1 = q0 + 8;
    float* out0 = g_att + ((size_t)b * T_SEQ + q0) * DIMC + h * DH;
    float* out1 = g_att + ((size_t)b * T_SEQ + q1) * DIMC + h * DH;
#pragma unroll
    for (int n = 0; n < 8; n++) {
        int cc = n * 8 + t4 * 2;
        out0[cc]     = f2tff(o[n][0] * inv0);
        out0[cc + 1] = f2tff(o[n][1] * inv0);
        out1[cc]     = f2tff(o[n][2] * inv1);
        out1[cc + 1] = f2tff(o[n][3] * inv1);
    }
}

// ---------------- 4) output GEMM + bias --------------------------------------
__global__ __launch_bounds__(256) void out_gemm(
    const float* __restrict__ bias, float* __restrict__ out)
{
    __shared__ float As[128][GS_STR];
    __shared__ float Bs[64][GS_STR];
    const int N = DIMC, K = DIMC;
    int tid = threadIdx.x, warp = tid >> 5, lane = tid & 31;
    int g = lane >> 2, t4 = lane & 3;
    int wm = warp >> 1, wn = warp & 1;
    int row0 = blockIdx.y * 128, col0 = blockIdx.x * 64;
    const float* A  = g_att;
    const float* Bt = g_wout_t;
    float c[2][4][4] = {};

    for (int k0 = 0; k0 < K; k0 += 32) {
#pragma unroll
        for (int t = 0; t < 4; t++) {
            int a = tid + t * 256;
            int r = a >> 3, c4 = (a & 7) * 4;
            *(float4*)&As[r][c4] = *(const float4*)(A + (size_t)(row0 + r) * K + k0 + c4);
        }
#pragma unroll
        for (int t = 0; t < 2; t++) {
            int a = tid + t * 256;
            int r = a >> 3, c4 = (a & 7) * 4;
            *(float4*)&Bs[r][c4] = *(const float4*)(Bt + (size_t)(col0 + r) * K + k0 + c4);
        }
        __syncthreads();
#pragma unroll
        for (int ks = 0; ks < 4; ks++) {
            int kb = ks * 8 + 2 * t4;
            float2 a01[2], a23[2], b[4];
#pragma unroll
            for (int mi = 0; mi < 2; mi++) {
                int rb = wm * 32 + mi * 16;
                a01[mi] = *(const float2*)&As[rb + g    ][kb];
                a23[mi] = *(const float2*)&As[rb + g + 8][kb];
            }
#pragma unroll
            for (int ni = 0; ni < 4; ni++)
                b[ni] = *(const float2*)&Bs[wn * 32 + ni * 8 + g][kb];
#pragma unroll
            for (int mi = 0; mi < 2; mi++)
#pragma unroll
                for (int ni = 0; ni < 4; ni++)
                    mma8(c[mi][ni], fu(a01[mi].x), fu(a23[mi].x),
                         fu(a01[mi].y), fu(a23[mi].y), fu(b[ni].x), fu(b[ni].y));
        }
        __syncthreads();
    }
#pragma unroll
    for (int mi = 0; mi < 2; mi++) {
        int r0 = row0 + wm * 32 + mi * 16 + g;
        int r1 = r0 + 8;
#pragma unroll
        for (int ni = 0; ni < 4; ni++) {
            int col = col0 + wn * 32 + ni * 8 + t4 * 2;
            float bz0 = bias[col], bz1 = bias[col + 1];
            out[(size_t)r0 * N + col]     = c[mi][ni][0] + bz0;
            out[(size_t)r0 * N + col + 1] = c[mi][ni][1] + bz1;
            out[(size_t)r1 * N + col]     = c[mi][ni][2] + bz0;
            out[(size_t)r1 * N + col + 1] = c[mi][ni][3] + bz1;
        }
    }
}

// ---------------- launch -----------------------------------------------------
extern "C" void kernel_launch(void* const* d_in, const int* in_sizes, int n_in,
                              void* d_out, int out_size)
{
    (void)in_sizes; (void)n_in; (void)out_size;
    const float* x     = (const float*)d_in[0];
    const float* ln_g  = (const float*)d_in[1];
    const float* ln_b  = (const float*)d_in[2];
    const float* w_qkv = (const float*)d_in[3];
    const float* w_out = (const float*)d_in[4];
    const float* b_out = (const float*)d_in[5];
    float* out = (float*)d_out;

    cudaFuncSetAttribute(attn_kernel,
                         cudaFuncAttributeMaxDynamicSharedMemorySize, ATTN_SMEM);

    float *wqkv_t, *wout_t;
    cudaGetSymbolAddress((void**)&wqkv_t, g_wqkv_t);
    cudaGetSymbolAddress((void**)&wout_t, g_wout_t);

    tr_cvt<<<dim3(3*DIMC/32, DIMC/32), dim3(32, 8)>>>(w_qkv, wqkv_t, DIMC, 3*DIMC);
    tr_cvt<<<dim3(DIMC/32, DIMC/32), dim3(32, 8)>>>(w_out, wout_t, DIMC, DIMC);
    ln_kernel<<<TOK / 8, 256>>>(x, ln_g, ln_b);
    qkv_gemm<<<dim3(3 * DIMC / 64, TOK / 128), 256>>>();
    attn_kernel<<<dim3(FRAMES, HEADS, BATCH), 128, ATTN_SMEM>>>();
    out_gemm<<<dim3(DIMC / 64, TOK / 128), 256>>>(b_out, out);
}

// round 6
// speedup vs baseline: 1.7476x; 1.1132x over previous
#include <cuda_runtime.h>
#include <math.h>

#define BATCH 4
#define T_SEQ 2048
#define TOK (BATCH*T_SEQ)          // 8192
#define DIMC 512
#define HEADS 8
#define DH 64
#define FRAMES 32

// ---------------- scratch (device globals: allocation-free rule) -------------
static __device__ float g_xn[TOK*DIMC];        // normalized x, tf32-rounded
static __device__ float g_q [TOK*DIMC];        // [B][H][T][64], tf32, pre-scaled 1/8
static __device__ float g_k [TOK*DIMC];        // [B][H][T][64], tf32
static __device__ float g_v [TOK*DIMC];        // [B][H][T][64], tf32
static __device__ float g_vt[TOK*DIMC];        // [B][H][64][T], tf32 (transposed V)
static __device__ float g_att[TOK*DIMC];       // attention out [B][T][H*64], tf32
static __device__ float g_wqkv_t[3*DIMC*DIMC]; // [1536][512] transposed, tf32
static __device__ float g_wout_t[DIMC*DIMC];   // [512][512]  transposed, tf32

// ---------------- tf32 helpers ----------------------------------------------
__device__ __forceinline__ unsigned f2tf(float x) {
    unsigned r; asm("cvt.rna.tf32.f32 %0, %1;" : "=r"(r) : "f"(x)); return r;
}
__device__ __forceinline__ float f2tff(float x) {
    return __uint_as_float(f2tf(x));
}
__device__ __forceinline__ unsigned fu(float x) { return __float_as_uint(x); }

// k-relabel convention: mma slot (t4, t4+4) <- logical k cols (2t4, 2t4+1).
__device__ __forceinline__ void mma8(float* c, unsigned a0, unsigned a1,
                                     unsigned a2, unsigned a3,
                                     unsigned b0, unsigned b1) {
    asm volatile(
        "mma.sync.aligned.m16n8k8.row.col.f32.tf32.tf32.f32 "
        "{%0,%1,%2,%3},{%4,%5,%6,%7},{%8,%9},{%0,%1,%2,%3};\n"
        : "+f"(c[0]), "+f"(c[1]), "+f"(c[2]), "+f"(c[3])
        : "r"(a0), "r"(a1), "r"(a2), "r"(a3), "r"(b0), "r"(b1));
}

// ---------------- 0) transpose + tf32-convert weights ------------------------
__global__ __launch_bounds__(256) void tr_cvt(
    const float* __restrict__ src, float* __restrict__ dst, int R, int C)
{
    __shared__ float t[32][33];
    int c0 = blockIdx.x * 32, r0 = blockIdx.y * 32;
    int tx = threadIdx.x, ty = threadIdx.y;       // 32 x 8
#pragma unroll
    for (int j = 0; j < 4; j++)
        t[ty + j*8][tx] = src[(size_t)(r0 + ty + j*8) * C + c0 + tx];
    __syncthreads();
#pragma unroll
    for (int j = 0; j < 4; j++)
        dst[(size_t)(c0 + ty + j*8) * R + r0 + tx] = f2tff(t[tx][ty + j*8]);
}

// ---------------- 0b) V transpose per (b,h): [T][64] -> [64][T] --------------
__global__ __launch_bounds__(256) void v_tr(void)
{
    __shared__ float t[32][33];
    int bh = blockIdx.z;
    const float* src = g_v  + (size_t)bh * T_SEQ * DH;
    float*       dst = g_vt + (size_t)bh * T_SEQ * DH;
    int t0 = blockIdx.x * 32, d0 = blockIdx.y * 32;
    int tx = threadIdx.x, ty = threadIdx.y;       // 32 x 8
#pragma unroll
    for (int j = 0; j < 4; j++)
        t[ty + j*8][tx] = src[(size_t)(t0 + ty + j*8) * DH + d0 + tx];
    __syncthreads();
#pragma unroll
    for (int j = 0; j < 4; j++)
        dst[(size_t)(d0 + ty + j*8) * T_SEQ + t0 + tx] = t[tx][ty + j*8];
}

// ---------------- 1) LayerNorm: one warp per token, tf32 output --------------
__global__ __launch_bounds__(256) void ln_kernel(
    const float* __restrict__ x, const float* __restrict__ gam,
    const float* __restrict__ bet)
{
    int warp = threadIdx.x >> 5, lane = threadIdx.x & 31;
    int tok  = blockIdx.x * 8 + warp;
    const float* xr = x + (size_t)tok * DIMC;
    float4 v[4]; float s = 0.f, ss = 0.f;
#pragma unroll
    for (int i = 0; i < 4; i++) {
        v[i] = *(const float4*)(xr + i * 128 + lane * 4);
        s  += v[i].x + v[i].y + v[i].z + v[i].w;
        ss += v[i].x*v[i].x + v[i].y*v[i].y + v[i].z*v[i].z + v[i].w*v[i].w;
    }
#pragma unroll
    for (int o = 16; o > 0; o >>= 1) {
        s  += __shfl_xor_sync(0xffffffffu, s, o);
        ss += __shfl_xor_sync(0xffffffffu, ss, o);
    }
    float mean = s * (1.f/512.f);
    float var  = ss * (1.f/512.f) - mean*mean;
    float rstd = rsqrtf(var + 1e-5f);
    float* orow = g_xn + (size_t)tok * DIMC;
#pragma unroll
    for (int i = 0; i < 4; i++) {
        int col = i * 128 + lane * 4;
        float4 g4 = *(const float4*)(gam + col);
        float4 b4 = *(const float4*)(bet + col);
        float4 r;
        r.x = f2tff((v[i].x - mean) * rstd * g4.x + b4.x);
        r.y = f2tff((v[i].y - mean) * rstd * g4.y + b4.y);
        r.z = f2tff((v[i].z - mean) * rstd * g4.z + b4.z);
        r.w = f2tff((v[i].w - mean) * rstd * g4.w + b4.w);
        *(float4*)(orow + col) = r;
    }
}

#define GS_STR 40   // (40*g + 2*t4) % 32 = 8g+2t4 -> conflict-free LDS.64

// ---------------- 2+4) GEMM core: 128x128 block, 64x32 warp tiles ------------
// A [M][K] row-major tf32, Bt [N][K] row-major tf32 (transposed weights).
template <int WHICH>   // 0 = qkv (epilogue scatter q/k/v), 1 = out (bias+store)
__global__ __launch_bounds__(256) void gemm128(
    const float* __restrict__ Ag, const float* __restrict__ Bt,
    const float* __restrict__ bias, float* __restrict__ outp)
{
    __shared__ float As[128][GS_STR];
    __shared__ float Bs[128][GS_STR];
    const int K = DIMC;
    int tid = threadIdx.x, warp = tid >> 5, lane = tid & 31;
    int g = lane >> 2, t4 = lane & 3;
    int wm = warp >> 2, wn = warp & 3;            // 2 x 4 warps
    int row0 = blockIdx.y * 128, col0 = blockIdx.x * 128;
    float c[4][4][4] = {};

    for (int k0 = 0; k0 < K; k0 += 32) {
#pragma unroll
        for (int t = 0; t < 4; t++) {
            int a = tid + t * 256;
            int r = a >> 3, c4 = (a & 7) * 4;
            *(float4*)&As[r][c4] = *(const float4*)(Ag + (size_t)(row0 + r) * K + k0 + c4);
            *(float4*)&Bs[r][c4] = *(const float4*)(Bt + (size_t)(col0 + r) * K + k0 + c4);
        }
        __syncthreads();
#pragma unroll
        for (int ks = 0; ks < 4; ks++) {
            int kb = ks * 8 + 2 * t4;
            float2 a01[4], a23[4], b[4];
#pragma unroll
            for (int mi = 0; mi < 4; mi++) {
                int rb = wm * 64 + mi * 16;
                a01[mi] = *(const float2*)&As[rb + g    ][kb];
                a23[mi] = *(const float2*)&As[rb + g + 8][kb];
            }
#pragma unroll
            for (int ni = 0; ni < 4; ni++)
                b[ni] = *(const float2*)&Bs[wn * 32 + ni * 8 + g][kb];
#pragma unroll
            for (int mi = 0; mi < 4; mi++)
#pragma unroll
                for (int ni = 0; ni < 4; ni++)
                    mma8(c[mi][ni], fu(a01[mi].x), fu(a23[mi].x),
                         fu(a01[mi].y), fu(a23[mi].y), fu(b[ni].x), fu(b[ni].y));
        }
        __syncthreads();
    }

#pragma unroll
    for (int mi = 0; mi < 4; mi++) {
        int r0 = row0 + wm * 64 + mi * 16 + g;
        int r1 = r0 + 8;
        if (WHICH == 0) {
            int bb = r0 >> 11;
            int t0i = r0 & 2047, t1i = r1 & 2047;
#pragma unroll
            for (int ni = 0; ni < 4; ni++) {
                int col = col0 + wn * 32 + ni * 8 + 2 * t4;
                int which = col >> 9;
                int hh = (col >> 6) & 7;
                float* dst = (which == 0) ? g_q : ((which == 1) ? g_k : g_v);
                float sc = (which == 0) ? 0.125f : 1.0f;
                size_t base = (((size_t)bb * HEADS + hh) * T_SEQ) * DH + (col & 63);
                size_t i0 = base + (size_t)t0i * DH;
                size_t i1 = base + (size_t)t1i * DH;
                dst[i0]     = f2tff(c[mi][ni][0] * sc);
                dst[i0 + 1] = f2tff(c[mi][ni][1] * sc);
                dst[i1]     = f2tff(c[mi][ni][2] * sc);
                dst[i1 + 1] = f2tff(c[mi][ni][3] * sc);
            }
        } else {
#pragma unroll
            for (int ni = 0; ni < 4; ni++) {
                int col = col0 + wn * 32 + ni * 8 + 2 * t4;
                float bz0 = bias[col], bz1 = bias[col + 1];
                outp[(size_t)r0 * DIMC + col]     = c[mi][ni][0] + bz0;
                outp[(size_t)r0 * DIMC + col + 1] = c[mi][ni][1] + bz1;
                outp[(size_t)r1 * DIMC + col]     = c[mi][ni][2] + bz0;
                outp[(size_t)r1 * DIMC + col + 1] = c[mi][ni][3] + bz1;
            }
        }
    }
}

// ---------------- 3) frame-causal flash attention ----------------------------
// K smem: [64 key][64 dh] stride 72; V smem (transposed): [64 dh][64 key] str 72.
// P stays entirely in registers (C-frag of QK == A-frag of PV under k-relabel).
#define KS_STR 72
#define ATTN_SMEM ((64*KS_STR + 64*KS_STR) * 4)

__global__ __launch_bounds__(128) void attn_kernel(void)
{
    extern __shared__ float sm[];
    float* Ks  = sm;                    // [64 key][64 dh]
    float* Vst = Ks + 64 * KS_STR;      // [64 dh][64 key]

    int f = 31 - blockIdx.x;            // heavy frames first
    int h = blockIdx.y, b = blockIdx.z;
    int tid = threadIdx.x, warp = tid >> 5, lane = tid & 31;
    int g = lane >> 2, t4 = lane & 3;
    size_t bh = ((size_t)b * HEADS + h) * T_SEQ * DH;
    const float* qb  = g_q  + bh;
    const float* kb  = g_k  + bh;
    const float* vtb = g_vt + bh;       // [64 dh][T]
    int t0 = f * 64;
    int wrow = warp * 16;

    // stage Q through Ks, pull this warp's a-fragments into registers
#pragma unroll
    for (int i = 0; i < 8; i++) {
        int a = tid + i * 128;
        int r = a >> 4, c4 = (a & 15) * 4;
        *(float4*)&Ks[r * KS_STR + c4] = *(const float4*)(qb + (size_t)(t0 + r) * DH + c4);
    }
    __syncthreads();
    float2 qa[8][2];
#pragma unroll
    for (int ks = 0; ks < 8; ks++) {
        int kc = ks * 8 + 2 * t4;
        qa[ks][0] = *(const float2*)&Ks[(wrow + g    ) * KS_STR + kc];
        qa[ks][1] = *(const float2*)&Ks[(wrow + g + 8) * KS_STR + kc];
    }
    __syncthreads();

    float m0 = -1e30f, m1 = -1e30f, l0 = 0.f, l1 = 0.f;
    float o[8][4] = {};

    for (int kt = 0; kt <= f; kt++) {
        int kt0 = kt * 64;
#pragma unroll
        for (int i = 0; i < 8; i++) {
            int a = tid + i * 128;
            int r = a >> 4, c4 = (a & 15) * 4;
            *(float4*)&Ks [r * KS_STR + c4] = *(const float4*)(kb  + (size_t)(kt0 + r) * DH + c4);
            *(float4*)&Vst[r * KS_STR + c4] = *(const float4*)(vtb + (size_t)r * T_SEQ + kt0 + c4);
        }
        __syncthreads();

        // S = Q K^T : 16 q rows x 64 keys per warp
        float s[8][4] = {};
#pragma unroll
        for (int ks = 0; ks < 8; ks++) {
            int kc = ks * 8 + 2 * t4;
#pragma unroll
            for (int n = 0; n < 8; n++) {
                float2 b2 = *(const float2*)&Ks[(n * 8 + g) * KS_STR + kc];
                mma8(s[n], fu(qa[ks][0].x), fu(qa[ks][1].x),
                     fu(qa[ks][0].y), fu(qa[ks][1].y), fu(b2.x), fu(b2.y));
            }
        }

        // online softmax (rows g, g+8 of this warp's strip)
        float mx0 = -1e30f, mx1 = -1e30f;
#pragma unroll
        for (int n = 0; n < 8; n++) {
            mx0 = fmaxf(mx0, fmaxf(s[n][0], s[n][1]));
            mx1 = fmaxf(mx1, fmaxf(s[n][2], s[n][3]));
        }
        mx0 = fmaxf(mx0, __shfl_xor_sync(0xffffffffu, mx0, 1));
        mx0 = fmaxf(mx0, __shfl_xor_sync(0xffffffffu, mx0, 2));
        mx1 = fmaxf(mx1, __shfl_xor_sync(0xffffffffu, mx1, 1));
        mx1 = fmaxf(mx1, __shfl_xor_sync(0xffffffffu, mx1, 2));
        float mn0 = fmaxf(m0, mx0), mn1 = fmaxf(m1, mx1);
        float al0 = __expf(m0 - mn0), al1 = __expf(m1 - mn1);
        float sum0 = 0.f, sum1 = 0.f;
#pragma unroll
        for (int n = 0; n < 8; n++) {
            s[n][0] = __expf(s[n][0] - mn0);
            s[n][1] = __expf(s[n][1] - mn0);
            s[n][2] = __expf(s[n][2] - mn1);
            s[n][3] = __expf(s[n][3] - mn1);
            sum0 += s[n][0] + s[n][1];
            sum1 += s[n][2] + s[n][3];
        }
        sum0 += __shfl_xor_sync(0xffffffffu, sum0, 1);
        sum0 += __shfl_xor_sync(0xffffffffu, sum0, 2);
        sum1 += __shfl_xor_sync(0xffffffffu, sum1, 1);
        sum1 += __shfl_xor_sync(0xffffffffu, sum1, 2);
        l0 = l0 * al0 + sum0;  l1 = l1 * al1 + sum1;
        m0 = mn0;  m1 = mn1;
#pragma unroll
        for (int n = 0; n < 8; n++) {
            o[n][0] *= al0; o[n][1] *= al0;
            o[n][2] *= al1; o[n][3] *= al1;
            // round P to tf32 in registers (same rounding point as before)
            s[n][0] = f2tff(s[n][0]);
            s[n][1] = f2tff(s[n][1]);
            s[n][2] = f2tff(s[n][2]);
            s[n][3] = f2tff(s[n][3]);
        }

        // O += P * V : C-frag s[ks] IS the A-frag for key-group ks.
        // a0 = P[row g][2t4] = s[ks][0], a1 = P[row g+8][2t4] = s[ks][2],
        // a2 = P[row g][2t4+1] = s[ks][1], a3 = s[ks][3].
#pragma unroll
        for (int ks = 0; ks < 8; ks++) {
            int kc = ks * 8 + 2 * t4;
#pragma unroll
            for (int n = 0; n < 8; n++) {
                float2 b2 = *(const float2*)&Vst[(n * 8 + g) * KS_STR + kc];
                mma8(o[n], fu(s[ks][0]), fu(s[ks][2]), fu(s[ks][1]), fu(s[ks][3]),
                     fu(b2.x), fu(b2.y));
            }
        }
        __syncthreads();
    }

    float inv0 = 1.f / l0, inv1 = 1.f / l1;
    int q0 = t0 + wrow + g, q1 = q0 + 8;
    float* out0 = g_att + ((size_t)b * T_SEQ + q0) * DIMC + h * DH;
    float* out1 = g_att + ((size_t)b * T_SEQ + q1) * DIMC + h * DH;
#pragma unroll
    for (int n = 0; n < 8; n++) {
        int cc = n * 8 + t4 * 2;
        out0[cc]     = f2tff(o[n][0] * inv0);
        out0[cc + 1] = f2tff(o[n][1] * inv0);
        out1[cc]     = f2tff(o[n][2] * inv1);
        out1[cc + 1] = f2tff(o[n][3] * inv1);
    }
}

// ---------------- launch -----------------------------------------------------
extern "C" void kernel_launch(void* const* d_in, const int* in_sizes, int n_in,
                              void* d_out, int out_size)
{
    (void)in_sizes; (void)n_in; (void)out_size;
    const float* x     = (const float*)d_in[0];
    const float* ln_g  = (const float*)d_in[1];
    const float* ln_b  = (const float*)d_in[2];
    const float* w_qkv = (const float*)d_in[3];
    const float* w_out = (const float*)d_in[4];
    const float* b_out = (const float*)d_in[5];
    float* out = (float*)d_out;

    cudaFuncSetAttribute(attn_kernel,
                         cudaFuncAttributeMaxDynamicSharedMemorySize, ATTN_SMEM);

    float *wqkv_t, *wout_t, *xn_p, *att_p;
    cudaGetSymbolAddress((void**)&wqkv_t, g_wqkv_t);
    cudaGetSymbolAddress((void**)&wout_t, g_wout_t);
    cudaGetSymbolAddress((void**)&xn_p,   g_xn);
    cudaGetSymbolAddress((void**)&att_p,  g_att);

    tr_cvt<<<dim3(3*DIMC/32, DIMC/32), dim3(32, 8)>>>(w_qkv, wqkv_t, DIMC, 3*DIMC);
    tr_cvt<<<dim3(DIMC/32, DIMC/32), dim3(32, 8)>>>(w_out, wout_t, DIMC, DIMC);
    ln_kernel<<<TOK / 8, 256>>>(x, ln_g, ln_b);
    gemm128<0><<<dim3(3 * DIMC / 128, TOK / 128), 256>>>(xn_p, wqkv_t, nullptr, nullptr);
    v_tr<<<dim3(T_SEQ / 32, DH / 32, BATCH * HEADS), dim3(32, 8)>>>();
    attn_kernel<<<dim3(FRAMES, HEADS, BATCH), 128, ATTN_SMEM>>>();
    gemm128<1><<<dim3(DIMC / 128, TOK / 128), 256>>>(att_p, wout_t, b_out, out);
}

// round 7
// speedup vs baseline: 2.0237x; 1.1580x over previous
#include <cuda_runtime.h>
#include <math.h>

#define BATCH 4
#define T_SEQ 2048
#define TOK (BATCH*T_SEQ)          // 8192
#define DIMC 512
#define HEADS 8
#define DH 64
#define FRAMES 32

// ---------------- scratch (device globals: allocation-free rule) -------------
static __device__ float g_xn[TOK*DIMC];        // normalized x, tf32-rounded
static __device__ float g_q [TOK*DIMC];        // [B][H][T][64], tf32, pre-scaled 1/8
static __device__ float g_k [TOK*DIMC];        // [B][H][T][64], tf32
static __device__ float g_v [TOK*DIMC];        // [B][H][T][64], tf32
static __device__ float g_vt[TOK*DIMC];        // [B][H][64][T], tf32 (transposed V)
static __device__ float g_att[TOK*DIMC];       // attention out [B][T][H*64], tf32
static __device__ float g_wqkv_t[3*DIMC*DIMC]; // [1536][512] transposed, tf32
static __device__ float g_wout_t[DIMC*DIMC];   // [512][512]  transposed, tf32

// ---------------- tf32 / cp.async helpers ------------------------------------
__device__ __forceinline__ unsigned f2tf(float x) {
    unsigned r; asm("cvt.rna.tf32.f32 %0, %1;" : "=r"(r) : "f"(x)); return r;
}
__device__ __forceinline__ float f2tff(float x) {
    return __uint_as_float(f2tf(x));
}
__device__ __forceinline__ unsigned fu(float x) { return __float_as_uint(x); }

__device__ __forceinline__ void cpa16(void* dst_smem, const void* src_gmem) {
    unsigned d = (unsigned)__cvta_generic_to_shared(dst_smem);
    asm volatile("cp.async.cg.shared.global [%0], [%1], 16;" :: "r"(d), "l"(src_gmem));
}
__device__ __forceinline__ void cpa_commit() {
    asm volatile("cp.async.commit_group;");
}
__device__ __forceinline__ void cpa_wait0() {
    asm volatile("cp.async.wait_group 0;");
}

// k-relabel convention: mma slot (t4, t4+4) <- logical k cols (2t4, 2t4+1).
__device__ __forceinline__ void mma8(float* c, unsigned a0, unsigned a1,
                                     unsigned a2, unsigned a3,
                                     unsigned b0, unsigned b1) {
    asm volatile(
        "mma.sync.aligned.m16n8k8.row.col.f32.tf32.tf32.f32 "
        "{%0,%1,%2,%3},{%4,%5,%6,%7},{%8,%9},{%0,%1,%2,%3};\n"
        : "+f"(c[0]), "+f"(c[1]), "+f"(c[2]), "+f"(c[3])
        : "r"(a0), "r"(a1), "r"(a2), "r"(a3), "r"(b0), "r"(b1));
}

// ---------------- 0) transpose + tf32-convert weights ------------------------
__global__ __launch_bounds__(256) void tr_cvt(
    const float* __restrict__ src, float* __restrict__ dst, int R, int C)
{
    __shared__ float t[32][33];
    int c0 = blockIdx.x * 32, r0 = blockIdx.y * 32;
    int tx = threadIdx.x, ty = threadIdx.y;       // 32 x 8
#pragma unroll
    for (int j = 0; j < 4; j++)
        t[ty + j*8][tx] = src[(size_t)(r0 + ty + j*8) * C + c0 + tx];
    __syncthreads();
#pragma unroll
    for (int j = 0; j < 4; j++)
        dst[(size_t)(c0 + ty + j*8) * R + r0 + tx] = f2tff(t[tx][ty + j*8]);
}

// ---------------- 0b) V transpose per (b,h): [T][64] -> [64][T] --------------
__global__ __launch_bounds__(256) void v_tr(void)
{
    __shared__ float t[32][33];
    int bh = blockIdx.z;
    const float* src = g_v  + (size_t)bh * T_SEQ * DH;
    float*       dst = g_vt + (size_t)bh * T_SEQ * DH;
    int t0 = blockIdx.x * 32, d0 = blockIdx.y * 32;
    int tx = threadIdx.x, ty = threadIdx.y;       // 32 x 8
#pragma unroll
    for (int j = 0; j < 4; j++)
        t[ty + j*8][tx] = src[(size_t)(t0 + ty + j*8) * DH + d0 + tx];
    __syncthreads();
#pragma unroll
    for (int j = 0; j < 4; j++)
        dst[(size_t)(d0 + ty + j*8) * T_SEQ + t0 + tx] = t[tx][ty + j*8];
}

// ---------------- 1) LayerNorm: one warp per token, tf32 output --------------
__global__ __launch_bounds__(256) void ln_kernel(
    const float* __restrict__ x, const float* __restrict__ gam,
    const float* __restrict__ bet)
{
    int warp = threadIdx.x >> 5, lane = threadIdx.x & 31;
    int tok  = blockIdx.x * 8 + warp;
    const float* xr = x + (size_t)tok * DIMC;
    float4 v[4]; float s = 0.f, ss = 0.f;
#pragma unroll
    for (int i = 0; i < 4; i++) {
        v[i] = *(const float4*)(xr + i * 128 + lane * 4);
        s  += v[i].x + v[i].y + v[i].z + v[i].w;
        ss += v[i].x*v[i].x + v[i].y*v[i].y + v[i].z*v[i].z + v[i].w*v[i].w;
    }
#pragma unroll
    for (int o = 16; o > 0; o >>= 1) {
        s  += __shfl_xor_sync(0xffffffffu, s, o);
        ss += __shfl_xor_sync(0xffffffffu, ss, o);
    }
    float mean = s * (1.f/512.f);
    float var  = ss * (1.f/512.f) - mean*mean;
    float rstd = rsqrtf(var + 1e-5f);
    float* orow = g_xn + (size_t)tok * DIMC;
#pragma unroll
    for (int i = 0; i < 4; i++) {
        int col = i * 128 + lane * 4;
        float4 g4 = *(const float4*)(gam + col);
        float4 b4 = *(const float4*)(bet + col);
        float4 r;
        r.x = f2tff((v[i].x - mean) * rstd * g4.x + b4.x);
        r.y = f2tff((v[i].y - mean) * rstd * g4.y + b4.y);
        r.z = f2tff((v[i].z - mean) * rstd * g4.z + b4.z);
        r.w = f2tff((v[i].w - mean) * rstd * g4.w + b4.w);
        *(float4*)(orow + col) = r;
    }
}

#define GS_STR 40   // (40*g + 2*t4) % 32 = 8g+2t4 -> conflict-free LDS.64
#define GEMM_SMEM (2 * 2 * 128 * GS_STR * 4)   // 2 stages x (As+Bs)

// ---------------- 2+4) GEMM: 128x128 block, cp.async double-buffered ---------
template <int WHICH>   // 0 = qkv (epilogue scatter q/k/v), 1 = out (bias+store)
__global__ __launch_bounds__(256) void gemm128(
    const float* __restrict__ Ag, const float* __restrict__ Bt,
    const float* __restrict__ bias, float* __restrict__ outp)
{
    extern __shared__ float smg[];
    float (*As)[128][GS_STR] = (float (*)[128][GS_STR])smg;
    float (*Bs)[128][GS_STR] = (float (*)[128][GS_STR])(smg + 2 * 128 * GS_STR);
    const int K = DIMC;
    int tid = threadIdx.x, warp = tid >> 5, lane = tid & 31;
    int g = lane >> 2, t4 = lane & 3;
    int wm = warp >> 2, wn = warp & 3;            // 2 x 4 warps
    int row0 = blockIdx.y * 128, col0 = blockIdx.x * 128;
    float c[4][4][4] = {};

    // per-thread load slots
    int lr = tid >> 3, lc = (tid & 7) * 4;

    // prologue: stage 0
#pragma unroll
    for (int t = 0; t < 4; t++) {
        int r = lr + t * 32;
        cpa16(&As[0][r][lc], Ag + (size_t)(row0 + r) * K + lc);
        cpa16(&Bs[0][r][lc], Bt + (size_t)(col0 + r) * K + lc);
    }
    cpa_commit();

    int buf = 0;
    for (int it = 0; it < 16; it++) {
        cpa_wait0();
        __syncthreads();
        if (it + 1 < 16) {
            int k0 = (it + 1) * 32;
#pragma unroll
            for (int t = 0; t < 4; t++) {
                int r = lr + t * 32;
                cpa16(&As[buf ^ 1][r][lc], Ag + (size_t)(row0 + r) * K + k0 + lc);
                cpa16(&Bs[buf ^ 1][r][lc], Bt + (size_t)(col0 + r) * K + k0 + lc);
            }
            cpa_commit();
        }
#pragma unroll
        for (int ks = 0; ks < 4; ks++) {
            int kb = ks * 8 + 2 * t4;
            float2 a01[4], a23[4], b[4];
#pragma unroll
            for (int mi = 0; mi < 4; mi++) {
                int rb = wm * 64 + mi * 16;
                a01[mi] = *(const float2*)&As[buf][rb + g    ][kb];
                a23[mi] = *(const float2*)&As[buf][rb + g + 8][kb];
            }
#pragma unroll
            for (int ni = 0; ni < 4; ni++)
                b[ni] = *(const float2*)&Bs[buf][wn * 32 + ni * 8 + g][kb];
#pragma unroll
            for (int mi = 0; mi < 4; mi++)
#pragma unroll
                for (int ni = 0; ni < 4; ni++)
                    mma8(c[mi][ni], fu(a01[mi].x), fu(a23[mi].x),
                         fu(a01[mi].y), fu(a23[mi].y), fu(b[ni].x), fu(b[ni].y));
        }
        buf ^= 1;
    }

#pragma unroll
    for (int mi = 0; mi < 4; mi++) {
        int r0 = row0 + wm * 64 + mi * 16 + g;
        int r1 = r0 + 8;
        if (WHICH == 0) {
            int bb = r0 >> 11;
            int t0i = r0 & 2047, t1i = r1 & 2047;
#pragma unroll
            for (int ni = 0; ni < 4; ni++) {
                int col = col0 + wn * 32 + ni * 8 + 2 * t4;
                int which = col >> 9;
                int hh = (col >> 6) & 7;
                float* dst = (which == 0) ? g_q : ((which == 1) ? g_k : g_v);
                float sc = (which == 0) ? 0.125f : 1.0f;
                size_t base = (((size_t)bb * HEADS + hh) * T_SEQ) * DH + (col & 63);
                size_t i0 = base + (size_t)t0i * DH;
                size_t i1 = base + (size_t)t1i * DH;
                dst[i0]     = f2tff(c[mi][ni][0] * sc);
                dst[i0 + 1] = f2tff(c[mi][ni][1] * sc);
                dst[i1]     = f2tff(c[mi][ni][2] * sc);
                dst[i1 + 1] = f2tff(c[mi][ni][3] * sc);
            }
        } else {
#pragma unroll
            for (int ni = 0; ni < 4; ni++) {
                int col = col0 + wn * 32 + ni * 8 + 2 * t4;
                float bz0 = bias[col], bz1 = bias[col + 1];
                outp[(size_t)r0 * DIMC + col]     = c[mi][ni][0] + bz0;
                outp[(size_t)r0 * DIMC + col + 1] = c[mi][ni][1] + bz1;
                outp[(size_t)r1 * DIMC + col]     = c[mi][ni][2] + bz0;
                outp[(size_t)r1 * DIMC + col + 1] = c[mi][ni][3] + bz1;
            }
        }
    }
}

// ---------------- 3) frame-causal flash attention ----------------------------
// 2-stage cp.async pipeline; P in registers; V transposed in smem.
#define KS_STR 72
#define ATTN_SMEM (2 * (64*KS_STR + 64*KS_STR) * 4)

__global__ __launch_bounds__(128) void attn_kernel(void)
{
    extern __shared__ float sm[];
    // layout: stage s: Ks at sm + s*STAGE, Vst at sm + s*STAGE + 64*KS_STR
    const int STAGE = 64 * KS_STR * 2;
    float* Ks0  = sm;
    float* Vs0  = sm + 64 * KS_STR;

    int f = 31 - blockIdx.x;            // heavy frames first
    int h = blockIdx.y, b = blockIdx.z;
    int tid = threadIdx.x, warp = tid >> 5, lane = tid & 31;
    int g = lane >> 2, t4 = lane & 3;
    size_t bh = ((size_t)b * HEADS + h) * T_SEQ * DH;
    const float* qb  = g_q  + bh;
    const float* kb  = g_k  + bh;
    const float* vtb = g_vt + bh;       // [64 dh][T]
    int t0 = f * 64;
    int wrow = warp * 16;
    int lr = tid >> 4, lc = (tid & 15) * 4;    // 8 rows per pass, 16 cols x4

    // stage Q through Ks0, pull this warp's a-fragments into registers
#pragma unroll
    for (int i = 0; i < 8; i++) {
        int r = lr + i * 8;
        *(float4*)&Ks0[r * KS_STR + lc] = *(const float4*)(qb + (size_t)(t0 + r) * DH + lc);
    }
    __syncthreads();
    float2 qa[8][2];
#pragma unroll
    for (int ks = 0; ks < 8; ks++) {
        int kc = ks * 8 + 2 * t4;
        qa[ks][0] = *(const float2*)&Ks0[(wrow + g    ) * KS_STR + kc];
        qa[ks][1] = *(const float2*)&Ks0[(wrow + g + 8) * KS_STR + kc];
    }
    __syncthreads();

    // prologue: async-load K/V tile 0 into stage 0
#pragma unroll
    for (int i = 0; i < 8; i++) {
        int r = lr + i * 8;
        cpa16(&Ks0[r * KS_STR + lc], kb  + (size_t)r * DH + lc);
        cpa16(&Vs0[r * KS_STR + lc], vtb + (size_t)r * T_SEQ + lc);
    }
    cpa_commit();

    float m0 = -1e30f, m1 = -1e30f, l0 = 0.f, l1 = 0.f;
    float o[8][4] = {};
    int buf = 0;

    for (int kt = 0; kt <= f; kt++) {
        cpa_wait0();
        __syncthreads();
        float* Ks  = sm + buf * STAGE;
        float* Vst = Ks + 64 * KS_STR;
        if (kt + 1 <= f) {
            int nt0 = (kt + 1) * 64;
            float* Kn = sm + (buf ^ 1) * STAGE;
            float* Vn = Kn + 64 * KS_STR;
#pragma unroll
            for (int i = 0; i < 8; i++) {
                int r = lr + i * 8;
                cpa16(&Kn[r * KS_STR + lc], kb  + (size_t)(nt0 + r) * DH + lc);
                cpa16(&Vn[r * KS_STR + lc], vtb + (size_t)r * T_SEQ + nt0 + lc);
            }
            cpa_commit();
        }

        // S = Q K^T : 16 q rows x 64 keys per warp
        float s[8][4] = {};
#pragma unroll
        for (int ks = 0; ks < 8; ks++) {
            int kc = ks * 8 + 2 * t4;
#pragma unroll
            for (int n = 0; n < 8; n++) {
                float2 b2 = *(const float2*)&Ks[(n * 8 + g) * KS_STR + kc];
                mma8(s[n], fu(qa[ks][0].x), fu(qa[ks][1].x),
                     fu(qa[ks][0].y), fu(qa[ks][1].y), fu(b2.x), fu(b2.y));
            }
        }

        // online softmax (rows g, g+8 of this warp's strip)
        float mx0 = -1e30f, mx1 = -1e30f;
#pragma unroll
        for (int n = 0; n < 8; n++) {
            mx0 = fmaxf(mx0, fmaxf(s[n][0], s[n][1]));
            mx1 = fmaxf(mx1, fmaxf(s[n][2], s[n][3]));
        }
        mx0 = fmaxf(mx0, __shfl_xor_sync(0xffffffffu, mx0, 1));
        mx0 = fmaxf(mx0, __shfl_xor_sync(0xffffffffu, mx0, 2));
        mx1 = fmaxf(mx1, __shfl_xor_sync(0xffffffffu, mx1, 1));
        mx1 = fmaxf(mx1, __shfl_xor_sync(0xffffffffu, mx1, 2));
        float mn0 = fmaxf(m0, mx0), mn1 = fmaxf(m1, mx1);
        float al0 = __expf(m0 - mn0), al1 = __expf(m1 - mn1);
        float sum0 = 0.f, sum1 = 0.f;
#pragma unroll
        for (int n = 0; n < 8; n++) {
            s[n][0] = __expf(s[n][0] - mn0);
            s[n][1] = __expf(s[n][1] - mn0);
            s[n][2] = __expf(s[n][2] - mn1);
            s[n][3] = __expf(s[n][3] - mn1);
            sum0 += s[n][0] + s[n][1];
            sum1 += s[n][2] + s[n][3];
        }
        sum0 += __shfl_xor_sync(0xffffffffu, sum0, 1);
        sum0 += __shfl_xor_sync(0xffffffffu, sum0, 2);
        sum1 += __shfl_xor_sync(0xffffffffu, sum1, 1);
        sum1 += __shfl_xor_sync(0xffffffffu, sum1, 2);
        l0 = l0 * al0 + sum0;  l1 = l1 * al1 + sum1;
        m0 = mn0;  m1 = mn1;
#pragma unroll
        for (int n = 0; n < 8; n++) {
            o[n][0] *= al0; o[n][1] *= al0;
            o[n][2] *= al1; o[n][3] *= al1;
            s[n][0] = f2tff(s[n][0]);
            s[n][1] = f2tff(s[n][1]);
            s[n][2] = f2tff(s[n][2]);
            s[n][3] = f2tff(s[n][3]);
        }

        // O += P * V : C-frag s[ks] IS the A-frag for key-group ks.
#pragma unroll
        for (int ks = 0; ks < 8; ks++) {
            int kc = ks * 8 + 2 * t4;
#pragma unroll
            for (int n = 0; n < 8; n++) {
                float2 b2 = *(const float2*)&Vst[(n * 8 + g) * KS_STR + kc];
                mma8(o[n], fu(s[ks][0]), fu(s[ks][2]), fu(s[ks][1]), fu(s[ks][3]),
                     fu(b2.x), fu(b2.y));
            }
        }
        buf ^= 1;
    }

    float inv0 = 1.f / l0, inv1 = 1.f / l1;
    int q0 = t0 + wrow + g, q1 = q0 + 8;
    float* out0 = g_att + ((size_t)b * T_SEQ + q0) * DIMC + h * DH;
    float* out1 = g_att + ((size_t)b * T_SEQ + q1) * DIMC + h * DH;
#pragma unroll
    for (int n = 0; n < 8; n++) {
        int cc = n * 8 + t4 * 2;
        out0[cc]     = f2tff(o[n][0] * inv0);
        out0[cc + 1] = f2tff(o[n][1] * inv0);
        out1[cc]     = f2tff(o[n][2] * inv1);
        out1[cc + 1] = f2tff(o[n][3] * inv1);
    }
}

// ---------------- launch -----------------------------------------------------
extern "C" void kernel_launch(void* const* d_in, const int* in_sizes, int n_in,
                              void* d_out, int out_size)
{
    (void)in_sizes; (void)n_in; (void)out_size;
    const float* x     = (const float*)d_in[0];
    const float* ln_g  = (const float*)d_in[1];
    const float* ln_b  = (const float*)d_in[2];
    const float* w_qkv = (const float*)d_in[3];
    const float* w_out = (const float*)d_in[4];
    const float* b_out = (const float*)d_in[5];
    float* out = (float*)d_out;

    cudaFuncSetAttribute(attn_kernel,
                         cudaFuncAttributeMaxDynamicSharedMemorySize, ATTN_SMEM);
    cudaFuncSetAttribute(gemm128<0>,
                         cudaFuncAttributeMaxDynamicSharedMemorySize, GEMM_SMEM);
    cudaFuncSetAttribute(gemm128<1>,
                         cudaFuncAttributeMaxDynamicSharedMemorySize, GEMM_SMEM);

    float *wqkv_t, *wout_t, *xn_p, *att_p;
    cudaGetSymbolAddress((void**)&wqkv_t, g_wqkv_t);
    cudaGetSymbolAddress((void**)&wout_t, g_wout_t);
    cudaGetSymbolAddress((void**)&xn_p,   g_xn);
    cudaGetSymbolAddress((void**)&att_p,  g_att);

    tr_cvt<<<dim3(3*DIMC/32, DIMC/32), dim3(32, 8)>>>(w_qkv, wqkv_t, DIMC, 3*DIMC);
    tr_cvt<<<dim3(DIMC/32, DIMC/32), dim3(32, 8)>>>(w_out, wout_t, DIMC, DIMC);
    ln_kernel<<<TOK / 8, 256>>>(x, ln_g, ln_b);
    gemm128<0><<<dim3(3 * DIMC / 128, TOK / 128), 256, GEMM_SMEM>>>(xn_p, wqkv_t, nullptr, nullptr);
    v_tr<<<dim3(T_SEQ / 32, DH / 32, BATCH * HEADS), dim3(32, 8)>>>();
    attn_kernel<<<dim3(FRAMES, HEADS, BATCH), 128, ATTN_SMEM>>>();
    gemm128<1><<<dim3(DIMC / 128, TOK / 128), 256, GEMM_SMEM>>>(att_p, wout_t, b_out, out);
}